// round 9
// baseline (speedup 1.0000x reference)
#include <cuda_runtime.h>
#include <cstddef>

// ---------------------------------------------------------------------------
// MultiHeadAttention forward, fp32, round 4: 128x128 / 8x8-microtile GEMMs,
// double-buffered smem, float4 LDS. Targets the L1-bound profile seen in R3
// (fma=36%, L1=94.5%): raise FFMA per LDS by ~6x.
//   B=2, S=2048, D=1024, H=16, Dh=64
// ---------------------------------------------------------------------------

#define BATCH   2
#define SEQ     2048
#define DMODEL  1024
#define HEADS   16
#define DHEAD   64
#define MROWS   (BATCH * SEQ)          // 4096
#define BH      (BATCH * HEADS)        // 32
#define KT      16                     // k-stage depth

// Scratch (static device globals: allocation-guard safe)
__device__ float g_q   [MROWS * DMODEL];
__device__ float g_k   [MROWS * DMODEL];
__device__ float g_v   [MROWS * DMODEL];
__device__ float g_attn[MROWS * DMODEL];
__device__ float g_sc  [(size_t)BH * SEQ * SEQ];   // 512 MB

// ---------------------------------------------------------------------------
// 128x128 NT GEMM body. C[M,N] = A[M,K] @ B[N,K]^T (+bias).
// 256 threads, 8x8 microtile, double-buffered KT=16 stages.
// Row stride 132 floats keeps 16B alignment for float4 LDS (132*4 % 16 == 0).
// ---------------------------------------------------------------------------
struct Smem128 {
    float As[2][KT][132];
    float Bs[2][KT][132];
};

__device__ __forceinline__ void gemm128_body(
    const float* __restrict__ A, int lda,
    const float* __restrict__ B, int ldb,
    float*       __restrict__ C, int ldc,
    int K, const float* __restrict__ bias,
    int m0, int n0, Smem128& s)
{
    const int tid = threadIdx.x;
    const int tx  = tid & 15;          // n micro group
    const int ty  = tid >> 4;          // m micro group
    const int lr  = tid >> 2;          // load row 0..63
    const int lk4 = (tid & 3) * 4;     // load k 0,4,8,12

    float acc[8][8] = {};

    // prologue: stage 0 -> smem buf 0
    {
        float4 a0 = *(const float4*)&A[(size_t)(m0 + lr)      * lda + lk4];
        float4 a1 = *(const float4*)&A[(size_t)(m0 + 64 + lr) * lda + lk4];
        float4 b0 = *(const float4*)&B[(size_t)(n0 + lr)      * ldb + lk4];
        float4 b1 = *(const float4*)&B[(size_t)(n0 + 64 + lr) * ldb + lk4];
        s.As[0][lk4+0][lr]    = a0.x; s.As[0][lk4+1][lr]    = a0.y;
        s.As[0][lk4+2][lr]    = a0.z; s.As[0][lk4+3][lr]    = a0.w;
        s.As[0][lk4+0][64+lr] = a1.x; s.As[0][lk4+1][64+lr] = a1.y;
        s.As[0][lk4+2][64+lr] = a1.z; s.As[0][lk4+3][64+lr] = a1.w;
        s.Bs[0][lk4+0][lr]    = b0.x; s.Bs[0][lk4+1][lr]    = b0.y;
        s.Bs[0][lk4+2][lr]    = b0.z; s.Bs[0][lk4+3][lr]    = b0.w;
        s.Bs[0][lk4+0][64+lr] = b1.x; s.Bs[0][lk4+1][64+lr] = b1.y;
        s.Bs[0][lk4+2][64+lr] = b1.z; s.Bs[0][lk4+3][64+lr] = b1.w;
    }
    __syncthreads();

    int buf = 0;
    for (int k0 = KT; k0 <= K; k0 += KT) {
        const bool has_next = (k0 < K);
        float4 a0n, a1n, b0n, b1n;
        if (has_next) {
            a0n = *(const float4*)&A[(size_t)(m0 + lr)      * lda + k0 + lk4];
            a1n = *(const float4*)&A[(size_t)(m0 + 64 + lr) * lda + k0 + lk4];
            b0n = *(const float4*)&B[(size_t)(n0 + lr)      * ldb + k0 + lk4];
            b1n = *(const float4*)&B[(size_t)(n0 + 64 + lr) * ldb + k0 + lk4];
        }

        #pragma unroll
        for (int kk = 0; kk < KT; kk++) {
            float4 av0 = *(const float4*)&s.As[buf][kk][ty * 4];
            float4 av1 = *(const float4*)&s.As[buf][kk][64 + ty * 4];
            float4 bv0 = *(const float4*)&s.Bs[buf][kk][tx * 4];
            float4 bv1 = *(const float4*)&s.Bs[buf][kk][64 + tx * 4];
            const float a[8] = {av0.x, av0.y, av0.z, av0.w, av1.x, av1.y, av1.z, av1.w};
            const float b[8] = {bv0.x, bv0.y, bv0.z, bv0.w, bv1.x, bv1.y, bv1.z, bv1.w};
            #pragma unroll
            for (int i = 0; i < 8; i++)
                #pragma unroll
                for (int j = 0; j < 8; j++)
                    acc[i][j] = fmaf(a[i], b[j], acc[i][j]);
        }

        if (has_next) {
            const int nb = buf ^ 1;
            s.As[nb][lk4+0][lr]    = a0n.x; s.As[nb][lk4+1][lr]    = a0n.y;
            s.As[nb][lk4+2][lr]    = a0n.z; s.As[nb][lk4+3][lr]    = a0n.w;
            s.As[nb][lk4+0][64+lr] = a1n.x; s.As[nb][lk4+1][64+lr] = a1n.y;
            s.As[nb][lk4+2][64+lr] = a1n.z; s.As[nb][lk4+3][64+lr] = a1n.w;
            s.Bs[nb][lk4+0][lr]    = b0n.x; s.Bs[nb][lk4+1][lr]    = b0n.y;
            s.Bs[nb][lk4+2][lr]    = b0n.z; s.Bs[nb][lk4+3][lr]    = b0n.w;
            s.Bs[nb][lk4+0][64+lr] = b1n.x; s.Bs[nb][lk4+1][64+lr] = b1n.y;
            s.Bs[nb][lk4+2][64+lr] = b1n.z; s.Bs[nb][lk4+3][64+lr] = b1n.w;
            __syncthreads();
        }
        buf ^= 1;
    }

    // epilogue: 16 float4 stores
    #pragma unroll
    for (int i = 0; i < 8; i++) {
        const int m = m0 + ((i < 4) ? (ty * 4 + i) : (64 + ty * 4 + i - 4));
        const int nA = n0 + tx * 4;
        const int nB = n0 + 64 + tx * 4;
        float4 r0 = make_float4(acc[i][0], acc[i][1], acc[i][2], acc[i][3]);
        float4 r1 = make_float4(acc[i][4], acc[i][5], acc[i][6], acc[i][7]);
        if (bias) {
            r0.x += bias[nA+0]; r0.y += bias[nA+1]; r0.z += bias[nA+2]; r0.w += bias[nA+3];
            r1.x += bias[nB+0]; r1.y += bias[nB+1]; r1.z += bias[nB+2]; r1.w += bias[nB+3];
        }
        *(float4*)&C[(size_t)m * ldc + nA] = r0;
        *(float4*)&C[(size_t)m * ldc + nB] = r1;
    }
}

// ---------------------------------------------------------------------------
// Projection GEMM: C[M,N] = A[M,K] @ W[N,K]^T (+bias). grid (N/128, M/128).
// ---------------------------------------------------------------------------
__global__ void __launch_bounds__(256, 2)
proj_kernel(const float* __restrict__ A,
            const float* __restrict__ W,
            float* __restrict__ C,
            const float* __restrict__ bias,
            int N, int K)
{
    __shared__ Smem128 s;
    gemm128_body(A, K, W, K, C, N, K, bias, blockIdx.y * 128, blockIdx.x * 128, s);
}

// ---------------------------------------------------------------------------
// scores[b,h] = q_bh @ k_bh^T.  grid (SEQ/128, SEQ/128, BH).
// ---------------------------------------------------------------------------
__global__ void __launch_bounds__(256, 2)
scores_kernel()
{
    __shared__ Smem128 s;
    const int bh = blockIdx.z;
    const int b  = bh >> 4;
    const int h  = bh & 15;
    const float* A = g_q + (size_t)b * SEQ * DMODEL + h * DHEAD;
    const float* B = g_k + (size_t)b * SEQ * DMODEL + h * DHEAD;
    float*       C = g_sc + (size_t)bh * SEQ * SEQ;
    gemm128_body(A, DMODEL, B, DMODEL, C, SEQ, DHEAD, nullptr,
                 blockIdx.y * 128, blockIdx.x * 128, s);
}

// ---------------------------------------------------------------------------
// Row softmax over SEQ=2048 columns. One 256-thread block per row, float4 I/O.
// ---------------------------------------------------------------------------
__global__ void __launch_bounds__(256)
softmax_kernel()
{
    __shared__ float red[8];
    const int tid  = threadIdx.x;
    const int lane = tid & 31;
    const int warp = tid >> 5;
    float4* p4 = reinterpret_cast<float4*>(g_sc + (size_t)blockIdx.x * SEQ);

    float4 x0 = p4[tid];
    float4 x1 = p4[tid + 256];

    float mx = fmaxf(fmaxf(fmaxf(x0.x, x0.y), fmaxf(x0.z, x0.w)),
                     fmaxf(fmaxf(x1.x, x1.y), fmaxf(x1.z, x1.w)));
    #pragma unroll
    for (int o = 16; o > 0; o >>= 1)
        mx = fmaxf(mx, __shfl_xor_sync(0xffffffffu, mx, o));
    if (lane == 0) red[warp] = mx;
    __syncthreads();
    if (warp == 0) {
        float m = red[lane & 7];
        #pragma unroll
        for (int o = 4; o > 0; o >>= 1)
            m = fmaxf(m, __shfl_xor_sync(0xffffffffu, m, o));
        if (lane == 0) red[0] = m;
    }
    __syncthreads();
    mx = red[0];
    __syncthreads();

    x0.x = __expf(x0.x - mx); x0.y = __expf(x0.y - mx);
    x0.z = __expf(x0.z - mx); x0.w = __expf(x0.w - mx);
    x1.x = __expf(x1.x - mx); x1.y = __expf(x1.y - mx);
    x1.z = __expf(x1.z - mx); x1.w = __expf(x1.w - mx);
    float sum = x0.x + x0.y + x0.z + x0.w + x1.x + x1.y + x1.z + x1.w;
    #pragma unroll
    for (int o = 16; o > 0; o >>= 1)
        sum += __shfl_xor_sync(0xffffffffu, sum, o);
    if (lane == 0) red[warp] = sum;
    __syncthreads();
    if (warp == 0) {
        float sm = red[lane & 7];
        #pragma unroll
        for (int o = 4; o > 0; o >>= 1)
            sm += __shfl_xor_sync(0xffffffffu, sm, o);
        if (lane == 0) red[0] = sm;
    }
    __syncthreads();
    const float inv = 1.0f / red[0];

    x0.x *= inv; x0.y *= inv; x0.z *= inv; x0.w *= inv;
    x1.x *= inv; x1.y *= inv; x1.z *= inv; x1.w *= inv;
    p4[tid]       = x0;
    p4[tid + 256] = x1;
}

// ---------------------------------------------------------------------------
// attn_bh (SEQ x 64) = P_bh (SEQ x SEQ) @ v_bh (SEQ x 64). NN GEMM.
// Tile 128x64, 256 threads, 8x4 microtile, double-buffered.
// grid (1, SEQ/128, BH).
// ---------------------------------------------------------------------------
__global__ void __launch_bounds__(256, 2)
pv_kernel()
{
    __shared__ float As[2][KT][132];
    __shared__ float Bs[2][KT][68];

    const int bh = blockIdx.z;
    const int b  = bh >> 4;
    const int h  = bh & 15;
    const float* A = g_sc   + (size_t)bh * SEQ * SEQ;                 // lda = SEQ
    const float* B = g_v    + (size_t)b * SEQ * DMODEL + h * DHEAD;   // ldb = DMODEL
    float*       C = g_attn + (size_t)b * SEQ * DMODEL + h * DHEAD;   // ldc = DMODEL

    const int tid = threadIdx.x;
    const int tx  = tid & 15;          // cols tx*4 .. tx*4+3
    const int ty  = tid >> 4;          // rows ty*4, 64+ty*4
    const int lr  = tid >> 2;          // A-load row 0..63
    const int lk4 = (tid & 3) * 4;     // A-load k 0,4,8,12
    const int bk  = tid >> 4;          // B-load k 0..15
    const int bn  = (tid & 15) * 4;    // B-load col

    const int m0 = blockIdx.y * 128;

    float acc[8][4] = {};

    // prologue
    {
        float4 a0 = *(const float4*)&A[(size_t)(m0 + lr)      * SEQ + lk4];
        float4 a1 = *(const float4*)&A[(size_t)(m0 + 64 + lr) * SEQ + lk4];
        float4 bv = *(const float4*)&B[(size_t)bk * DMODEL + bn];
        As[0][lk4+0][lr]    = a0.x; As[0][lk4+1][lr]    = a0.y;
        As[0][lk4+2][lr]    = a0.z; As[0][lk4+3][lr]    = a0.w;
        As[0][lk4+0][64+lr] = a1.x; As[0][lk4+1][64+lr] = a1.y;
        As[0][lk4+2][64+lr] = a1.z; As[0][lk4+3][64+lr] = a1.w;
        *(float4*)&Bs[0][bk][bn] = bv;
    }
    __syncthreads();

    int buf = 0;
    for (int k0 = KT; k0 <= SEQ; k0 += KT) {
        const bool has_next = (k0 < SEQ);
        float4 a0n, a1n, bvn;
        if (has_next) {
            a0n = *(const float4*)&A[(size_t)(m0 + lr)      * SEQ + k0 + lk4];
            a1n = *(const float4*)&A[(size_t)(m0 + 64 + lr) * SEQ + k0 + lk4];
            bvn = *(const float4*)&B[(size_t)(k0 + bk) * DMODEL + bn];
        }

        #pragma unroll
        for (int kk = 0; kk < KT; kk++) {
            float4 av0 = *(const float4*)&As[buf][kk][ty * 4];
            float4 av1 = *(const float4*)&As[buf][kk][64 + ty * 4];
            float4 bv  = *(const float4*)&Bs[buf][kk][tx * 4];
            const float a[8] = {av0.x, av0.y, av0.z, av0.w, av1.x, av1.y, av1.z, av1.w};
            const float bb[4] = {bv.x, bv.y, bv.z, bv.w};
            #pragma unroll
            for (int i = 0; i < 8; i++)
                #pragma unroll
                for (int j = 0; j < 4; j++)
                    acc[i][j] = fmaf(a[i], bb[j], acc[i][j]);
        }

        if (has_next) {
            const int nb = buf ^ 1;
            As[nb][lk4+0][lr]    = a0n.x; As[nb][lk4+1][lr]    = a0n.y;
            As[nb][lk4+2][lr]    = a0n.z; As[nb][lk4+3][lr]    = a0n.w;
            As[nb][lk4+0][64+lr] = a1n.x; As[nb][lk4+1][64+lr] = a1n.y;
            As[nb][lk4+2][64+lr] = a1n.z; As[nb][lk4+3][64+lr] = a1n.w;
            *(float4*)&Bs[nb][bk][bn] = bvn;
            __syncthreads();
        }
        buf ^= 1;
    }

    #pragma unroll
    for (int i = 0; i < 8; i++) {
        const int m = m0 + ((i < 4) ? (ty * 4 + i) : (64 + ty * 4 + i - 4));
        *(float4*)&C[(size_t)m * DMODEL + tx * 4] =
            make_float4(acc[i][0], acc[i][1], acc[i][2], acc[i][3]);
    }
}

// ---------------------------------------------------------------------------
extern "C" void kernel_launch(void* const* d_in, const int* in_sizes, int n_in,
                              void* d_out, int out_size)
{
    const float* x  = (const float*)d_in[0];
    // d_in[1] = attn_weights (unused by reference forward)
    const float* Wq = (const float*)d_in[2];
    const float* Wk = (const float*)d_in[3];
    const float* Wv = (const float*)d_in[4];
    const float* Wp = (const float*)d_in[5];
    const float* bp = (const float*)d_in[6];
    float* out = (float*)d_out;

    float *q, *k, *v, *attn;
    cudaGetSymbolAddress((void**)&q,    g_q);
    cudaGetSymbolAddress((void**)&k,    g_k);
    cudaGetSymbolAddress((void**)&v,    g_v);
    cudaGetSymbolAddress((void**)&attn, g_attn);

    const dim3 blk(256);
    const dim3 grid_proj(DMODEL / 128, MROWS / 128);   // (8, 32)

    // QKV projections
    proj_kernel<<<grid_proj, blk>>>(x, Wq, q, nullptr, DMODEL, DMODEL);
    proj_kernel<<<grid_proj, blk>>>(x, Wk, k, nullptr, DMODEL, DMODEL);
    proj_kernel<<<grid_proj, blk>>>(x, Wv, v, nullptr, DMODEL, DMODEL);

    // Attention
    scores_kernel <<<dim3(SEQ / 128, SEQ / 128, BH), blk>>>();
    softmax_kernel<<<BH * SEQ, blk>>>();
    pv_kernel     <<<dim3(1, SEQ / 128, BH), blk>>>();

    // Output projection (+bias)
    proj_kernel<<<grid_proj, blk>>>(attn, Wp, out, bp, DMODEL, DMODEL);
}

// round 10
// speedup vs baseline: 1.0039x; 1.0039x over previous
#include <cuda_runtime.h>
#include <cstddef>

// ---------------------------------------------------------------------------
// MultiHeadAttention forward, fp32, round 4: 128x128 / 8x8-microtile GEMMs,
// double-buffered smem, float4 LDS. Targets the L1-bound profile seen in R3
// (fma=36%, L1=94.5%): raise FFMA per LDS by ~6x.
//   B=2, S=2048, D=1024, H=16, Dh=64
// ---------------------------------------------------------------------------

#define BATCH   2
#define SEQ     2048
#define DMODEL  1024
#define HEADS   16
#define DHEAD   64
#define MROWS   (BATCH * SEQ)          // 4096
#define BH      (BATCH * HEADS)        // 32
#define KT      16                     // k-stage depth

// Scratch (static device globals: allocation-guard safe)
__device__ float g_q   [MROWS * DMODEL];
__device__ float g_k   [MROWS * DMODEL];
__device__ float g_v   [MROWS * DMODEL];
__device__ float g_attn[MROWS * DMODEL];
__device__ float g_sc  [(size_t)BH * SEQ * SEQ];   // 512 MB

// ---------------------------------------------------------------------------
// 128x128 NT GEMM body. C[M,N] = A[M,K] @ B[N,K]^T (+bias).
// 256 threads, 8x8 microtile, double-buffered KT=16 stages.
// Row stride 132 floats keeps 16B alignment for float4 LDS (132*4 % 16 == 0).
// ---------------------------------------------------------------------------
struct Smem128 {
    float As[2][KT][132];
    float Bs[2][KT][132];
};

__device__ __forceinline__ void gemm128_body(
    const float* __restrict__ A, int lda,
    const float* __restrict__ B, int ldb,
    float*       __restrict__ C, int ldc,
    int K, const float* __restrict__ bias,
    int m0, int n0, Smem128& s)
{
    const int tid = threadIdx.x;
    const int tx  = tid & 15;          // n micro group
    const int ty  = tid >> 4;          // m micro group
    const int lr  = tid >> 2;          // load row 0..63
    const int lk4 = (tid & 3) * 4;     // load k 0,4,8,12

    float acc[8][8] = {};

    // prologue: stage 0 -> smem buf 0
    {
        float4 a0 = *(const float4*)&A[(size_t)(m0 + lr)      * lda + lk4];
        float4 a1 = *(const float4*)&A[(size_t)(m0 + 64 + lr) * lda + lk4];
        float4 b0 = *(const float4*)&B[(size_t)(n0 + lr)      * ldb + lk4];
        float4 b1 = *(const float4*)&B[(size_t)(n0 + 64 + lr) * ldb + lk4];
        s.As[0][lk4+0][lr]    = a0.x; s.As[0][lk4+1][lr]    = a0.y;
        s.As[0][lk4+2][lr]    = a0.z; s.As[0][lk4+3][lr]    = a0.w;
        s.As[0][lk4+0][64+lr] = a1.x; s.As[0][lk4+1][64+lr] = a1.y;
        s.As[0][lk4+2][64+lr] = a1.z; s.As[0][lk4+3][64+lr] = a1.w;
        s.Bs[0][lk4+0][lr]    = b0.x; s.Bs[0][lk4+1][lr]    = b0.y;
        s.Bs[0][lk4+2][lr]    = b0.z; s.Bs[0][lk4+3][lr]    = b0.w;
        s.Bs[0][lk4+0][64+lr] = b1.x; s.Bs[0][lk4+1][64+lr] = b1.y;
        s.Bs[0][lk4+2][64+lr] = b1.z; s.Bs[0][lk4+3][64+lr] = b1.w;
    }
    __syncthreads();

    int buf = 0;
    for (int k0 = KT; k0 <= K; k0 += KT) {
        const bool has_next = (k0 < K);
        float4 a0n, a1n, b0n, b1n;
        if (has_next) {
            a0n = *(const float4*)&A[(size_t)(m0 + lr)      * lda + k0 + lk4];
            a1n = *(const float4*)&A[(size_t)(m0 + 64 + lr) * lda + k0 + lk4];
            b0n = *(const float4*)&B[(size_t)(n0 + lr)      * ldb + k0 + lk4];
            b1n = *(const float4*)&B[(size_t)(n0 + 64 + lr) * ldb + k0 + lk4];
        }

        #pragma unroll
        for (int kk = 0; kk < KT; kk++) {
            float4 av0 = *(const float4*)&s.As[buf][kk][ty * 4];
            float4 av1 = *(const float4*)&s.As[buf][kk][64 + ty * 4];
            float4 bv0 = *(const float4*)&s.Bs[buf][kk][tx * 4];
            float4 bv1 = *(const float4*)&s.Bs[buf][kk][64 + tx * 4];
            const float a[8] = {av0.x, av0.y, av0.z, av0.w, av1.x, av1.y, av1.z, av1.w};
            const float b[8] = {bv0.x, bv0.y, bv0.z, bv0.w, bv1.x, bv1.y, bv1.z, bv1.w};
            #pragma unroll
            for (int i = 0; i < 8; i++)
                #pragma unroll
                for (int j = 0; j < 8; j++)
                    acc[i][j] = fmaf(a[i], b[j], acc[i][j]);
        }

        if (has_next) {
            const int nb = buf ^ 1;
            s.As[nb][lk4+0][lr]    = a0n.x; s.As[nb][lk4+1][lr]    = a0n.y;
            s.As[nb][lk4+2][lr]    = a0n.z; s.As[nb][lk4+3][lr]    = a0n.w;
            s.As[nb][lk4+0][64+lr] = a1n.x; s.As[nb][lk4+1][64+lr] = a1n.y;
            s.As[nb][lk4+2][64+lr] = a1n.z; s.As[nb][lk4+3][64+lr] = a1n.w;
            s.Bs[nb][lk4+0][lr]    = b0n.x; s.Bs[nb][lk4+1][lr]    = b0n.y;
            s.Bs[nb][lk4+2][lr]    = b0n.z; s.Bs[nb][lk4+3][lr]    = b0n.w;
            s.Bs[nb][lk4+0][64+lr] = b1n.x; s.Bs[nb][lk4+1][64+lr] = b1n.y;
            s.Bs[nb][lk4+2][64+lr] = b1n.z; s.Bs[nb][lk4+3][64+lr] = b1n.w;
            __syncthreads();
        }
        buf ^= 1;
    }

    // epilogue: 16 float4 stores
    #pragma unroll
    for (int i = 0; i < 8; i++) {
        const int m = m0 + ((i < 4) ? (ty * 4 + i) : (64 + ty * 4 + i - 4));
        const int nA = n0 + tx * 4;
        const int nB = n0 + 64 + tx * 4;
        float4 r0 = make_float4(acc[i][0], acc[i][1], acc[i][2], acc[i][3]);
        float4 r1 = make_float4(acc[i][4], acc[i][5], acc[i][6], acc[i][7]);
        if (bias) {
            r0.x += bias[nA+0]; r0.y += bias[nA+1]; r0.z += bias[nA+2]; r0.w += bias[nA+3];
            r1.x += bias[nB+0]; r1.y += bias[nB+1]; r1.z += bias[nB+2]; r1.w += bias[nB+3];
        }
        *(float4*)&C[(size_t)m * ldc + nA] = r0;
        *(float4*)&C[(size_t)m * ldc + nB] = r1;
    }
}

// ---------------------------------------------------------------------------
// Projection GEMM: C[M,N] = A[M,K] @ W[N,K]^T (+bias). grid (N/128, M/128).
// ---------------------------------------------------------------------------
__global__ void __launch_bounds__(256, 2)
proj_kernel(const float* __restrict__ A,
            const float* __restrict__ W,
            float* __restrict__ C,
            const float* __restrict__ bias,
            int N, int K)
{
    __shared__ Smem128 s;
    gemm128_body(A, K, W, K, C, N, K, bias, blockIdx.y * 128, blockIdx.x * 128, s);
}

// ---------------------------------------------------------------------------
// scores[b,h] = q_bh @ k_bh^T.  grid (SEQ/128, SEQ/128, BH).
// ---------------------------------------------------------------------------
__global__ void __launch_bounds__(256, 2)
scores_kernel()
{
    __shared__ Smem128 s;
    const int bh = blockIdx.z;
    const int b  = bh >> 4;
    const int h  = bh & 15;
    const float* A = g_q + (size_t)b * SEQ * DMODEL + h * DHEAD;
    const float* B = g_k + (size_t)b * SEQ * DMODEL + h * DHEAD;
    float*       C = g_sc + (size_t)bh * SEQ * SEQ;
    gemm128_body(A, DMODEL, B, DMODEL, C, SEQ, DHEAD, nullptr,
                 blockIdx.y * 128, blockIdx.x * 128, s);
}

// ---------------------------------------------------------------------------
// Row softmax over SEQ=2048 columns. One 256-thread block per row, float4 I/O.
// ---------------------------------------------------------------------------
__global__ void __launch_bounds__(256)
softmax_kernel()
{
    __shared__ float red[8];
    const int tid  = threadIdx.x;
    const int lane = tid & 31;
    const int warp = tid >> 5;
    float4* p4 = reinterpret_cast<float4*>(g_sc + (size_t)blockIdx.x * SEQ);

    float4 x0 = p4[tid];
    float4 x1 = p4[tid + 256];

    float mx = fmaxf(fmaxf(fmaxf(x0.x, x0.y), fmaxf(x0.z, x0.w)),
                     fmaxf(fmaxf(x1.x, x1.y), fmaxf(x1.z, x1.w)));
    #pragma unroll
    for (int o = 16; o > 0; o >>= 1)
        mx = fmaxf(mx, __shfl_xor_sync(0xffffffffu, mx, o));
    if (lane == 0) red[warp] = mx;
    __syncthreads();
    if (warp == 0) {
        float m = red[lane & 7];
        #pragma unroll
        for (int o = 4; o > 0; o >>= 1)
            m = fmaxf(m, __shfl_xor_sync(0xffffffffu, m, o));
        if (lane == 0) red[0] = m;
    }
    __syncthreads();
    mx = red[0];
    __syncthreads();

    x0.x = __expf(x0.x - mx); x0.y = __expf(x0.y - mx);
    x0.z = __expf(x0.z - mx); x0.w = __expf(x0.w - mx);
    x1.x = __expf(x1.x - mx); x1.y = __expf(x1.y - mx);
    x1.z = __expf(x1.z - mx); x1.w = __expf(x1.w - mx);
    float sum = x0.x + x0.y + x0.z + x0.w + x1.x + x1.y + x1.z + x1.w;
    #pragma unroll
    for (int o = 16; o > 0; o >>= 1)
        sum += __shfl_xor_sync(0xffffffffu, sum, o);
    if (lane == 0) red[warp] = sum;
    __syncthreads();
    if (warp == 0) {
        float sm = red[lane & 7];
        #pragma unroll
        for (int o = 4; o > 0; o >>= 1)
            sm += __shfl_xor_sync(0xffffffffu, sm, o);
        if (lane == 0) red[0] = sm;
    }
    __syncthreads();
    const float inv = 1.0f / red[0];

    x0.x *= inv; x0.y *= inv; x0.z *= inv; x0.w *= inv;
    x1.x *= inv; x1.y *= inv; x1.z *= inv; x1.w *= inv;
    p4[tid]       = x0;
    p4[tid + 256] = x1;
}

// ---------------------------------------------------------------------------
// attn_bh (SEQ x 64) = P_bh (SEQ x SEQ) @ v_bh (SEQ x 64). NN GEMM.
// Tile 128x64, 256 threads, 8x4 microtile, double-buffered.
// grid (1, SEQ/128, BH).
// ---------------------------------------------------------------------------
__global__ void __launch_bounds__(256, 2)
pv_kernel()
{
    __shared__ float As[2][KT][132];
    __shared__ float Bs[2][KT][68];

    const int bh = blockIdx.z;
    const int b  = bh >> 4;
    const int h  = bh & 15;
    const float* A = g_sc   + (size_t)bh * SEQ * SEQ;                 // lda = SEQ
    const float* B = g_v    + (size_t)b * SEQ * DMODEL + h * DHEAD;   // ldb = DMODEL
    float*       C = g_attn + (size_t)b * SEQ * DMODEL + h * DHEAD;   // ldc = DMODEL

    const int tid = threadIdx.x;
    const int tx  = tid & 15;          // cols tx*4 .. tx*4+3
    const int ty  = tid >> 4;          // rows ty*4, 64+ty*4
    const int lr  = tid >> 2;          // A-load row 0..63
    const int lk4 = (tid & 3) * 4;     // A-load k 0,4,8,12
    const int bk  = tid >> 4;          // B-load k 0..15
    const int bn  = (tid & 15) * 4;    // B-load col

    const int m0 = blockIdx.y * 128;

    float acc[8][4] = {};

    // prologue
    {
        float4 a0 = *(const float4*)&A[(size_t)(m0 + lr)      * SEQ + lk4];
        float4 a1 = *(const float4*)&A[(size_t)(m0 + 64 + lr) * SEQ + lk4];
        float4 bv = *(const float4*)&B[(size_t)bk * DMODEL + bn];
        As[0][lk4+0][lr]    = a0.x; As[0][lk4+1][lr]    = a0.y;
        As[0][lk4+2][lr]    = a0.z; As[0][lk4+3][lr]    = a0.w;
        As[0][lk4+0][64+lr] = a1.x; As[0][lk4+1][64+lr] = a1.y;
        As[0][lk4+2][64+lr] = a1.z; As[0][lk4+3][64+lr] = a1.w;
        *(float4*)&Bs[0][bk][bn] = bv;
    }
    __syncthreads();

    int buf = 0;
    for (int k0 = KT; k0 <= SEQ; k0 += KT) {
        const bool has_next = (k0 < SEQ);
        float4 a0n, a1n, bvn;
        if (has_next) {
            a0n = *(const float4*)&A[(size_t)(m0 + lr)      * SEQ + k0 + lk4];
            a1n = *(const float4*)&A[(size_t)(m0 + 64 + lr) * SEQ + k0 + lk4];
            bvn = *(const float4*)&B[(size_t)(k0 + bk) * DMODEL + bn];
        }

        #pragma unroll
        for (int kk = 0; kk < KT; kk++) {
            float4 av0 = *(const float4*)&As[buf][kk][ty * 4];
            float4 av1 = *(const float4*)&As[buf][kk][64 + ty * 4];
            float4 bv  = *(const float4*)&Bs[buf][kk][tx * 4];
            const float a[8] = {av0.x, av0.y, av0.z, av0.w, av1.x, av1.y, av1.z, av1.w};
            const float bb[4] = {bv.x, bv.y, bv.z, bv.w};
            #pragma unroll
            for (int i = 0; i < 8; i++)
                #pragma unroll
                for (int j = 0; j < 4; j++)
                    acc[i][j] = fmaf(a[i], bb[j], acc[i][j]);
        }

        if (has_next) {
            const int nb = buf ^ 1;
            As[nb][lk4+0][lr]    = a0n.x; As[nb][lk4+1][lr]    = a0n.y;
            As[nb][lk4+2][lr]    = a0n.z; As[nb][lk4+3][lr]    = a0n.w;
            As[nb][lk4+0][64+lr] = a1n.x; As[nb][lk4+1][64+lr] = a1n.y;
            As[nb][lk4+2][64+lr] = a1n.z; As[nb][lk4+3][64+lr] = a1n.w;
            *(float4*)&Bs[nb][bk][bn] = bvn;
            __syncthreads();
        }
        buf ^= 1;
    }

    #pragma unroll
    for (int i = 0; i < 8; i++) {
        const int m = m0 + ((i < 4) ? (ty * 4 + i) : (64 + ty * 4 + i - 4));
        *(float4*)&C[(size_t)m * DMODEL + tx * 4] =
            make_float4(acc[i][0], acc[i][1], acc[i][2], acc[i][3]);
    }
}

// ---------------------------------------------------------------------------
extern "C" void kernel_launch(void* const* d_in, const int* in_sizes, int n_in,
                              void* d_out, int out_size)
{
    const float* x  = (const float*)d_in[0];
    // d_in[1] = attn_weights (unused by reference forward)
    const float* Wq = (const float*)d_in[2];
    const float* Wk = (const float*)d_in[3];
    const float* Wv = (const float*)d_in[4];
    const float* Wp = (const float*)d_in[5];
    const float* bp = (const float*)d_in[6];
    float* out = (float*)d_out;

    float *q, *k, *v, *attn;
    cudaGetSymbolAddress((void**)&q,    g_q);
    cudaGetSymbolAddress((void**)&k,    g_k);
    cudaGetSymbolAddress((void**)&v,    g_v);
    cudaGetSymbolAddress((void**)&attn, g_attn);

    const dim3 blk(256);
    const dim3 grid_proj(DMODEL / 128, MROWS / 128);   // (8, 32)

    // QKV projections
    proj_kernel<<<grid_proj, blk>>>(x, Wq, q, nullptr, DMODEL, DMODEL);
    proj_kernel<<<grid_proj, blk>>>(x, Wk, k, nullptr, DMODEL, DMODEL);
    proj_kernel<<<grid_proj, blk>>>(x, Wv, v, nullptr, DMODEL, DMODEL);

    // Attention
    scores_kernel <<<dim3(SEQ / 128, SEQ / 128, BH), blk>>>();
    softmax_kernel<<<BH * SEQ, blk>>>();
    pv_kernel     <<<dim3(1, SEQ / 128, BH), blk>>>();

    // Output projection (+bias)
    proj_kernel<<<grid_proj, blk>>>(attn, Wp, out, bp, DMODEL, DMODEL);
}

// round 11
// speedup vs baseline: 1.0043x; 1.0004x over previous
#include <cuda_runtime.h>
#include <cstddef>

// ---------------------------------------------------------------------------
// MultiHeadAttention forward, fp32, round 4: 128x128 / 8x8-microtile GEMMs,
// double-buffered smem, float4 LDS. Targets the L1-bound profile seen in R3
// (fma=36%, L1=94.5%): raise FFMA per LDS by ~6x.
//   B=2, S=2048, D=1024, H=16, Dh=64
// ---------------------------------------------------------------------------

#define BATCH   2
#define SEQ     2048
#define DMODEL  1024
#define HEADS   16
#define DHEAD   64
#define MROWS   (BATCH * SEQ)          // 4096
#define BH      (BATCH * HEADS)        // 32
#define KT      16                     // k-stage depth

// Scratch (static device globals: allocation-guard safe)
__device__ float g_q   [MROWS * DMODEL];
__device__ float g_k   [MROWS * DMODEL];
__device__ float g_v   [MROWS * DMODEL];
__device__ float g_attn[MROWS * DMODEL];
__device__ float g_sc  [(size_t)BH * SEQ * SEQ];   // 512 MB

// ---------------------------------------------------------------------------
// 128x128 NT GEMM body. C[M,N] = A[M,K] @ B[N,K]^T (+bias).
// 256 threads, 8x8 microtile, double-buffered KT=16 stages.
// Row stride 132 floats keeps 16B alignment for float4 LDS (132*4 % 16 == 0).
// ---------------------------------------------------------------------------
struct Smem128 {
    float As[2][KT][132];
    float Bs[2][KT][132];
};

__device__ __forceinline__ void gemm128_body(
    const float* __restrict__ A, int lda,
    const float* __restrict__ B, int ldb,
    float*       __restrict__ C, int ldc,
    int K, const float* __restrict__ bias,
    int m0, int n0, Smem128& s)
{
    const int tid = threadIdx.x;
    const int tx  = tid & 15;          // n micro group
    const int ty  = tid >> 4;          // m micro group
    const int lr  = tid >> 2;          // load row 0..63
    const int lk4 = (tid & 3) * 4;     // load k 0,4,8,12

    float acc[8][8] = {};

    // prologue: stage 0 -> smem buf 0
    {
        float4 a0 = *(const float4*)&A[(size_t)(m0 + lr)      * lda + lk4];
        float4 a1 = *(const float4*)&A[(size_t)(m0 + 64 + lr) * lda + lk4];
        float4 b0 = *(const float4*)&B[(size_t)(n0 + lr)      * ldb + lk4];
        float4 b1 = *(const float4*)&B[(size_t)(n0 + 64 + lr) * ldb + lk4];
        s.As[0][lk4+0][lr]    = a0.x; s.As[0][lk4+1][lr]    = a0.y;
        s.As[0][lk4+2][lr]    = a0.z; s.As[0][lk4+3][lr]    = a0.w;
        s.As[0][lk4+0][64+lr] = a1.x; s.As[0][lk4+1][64+lr] = a1.y;
        s.As[0][lk4+2][64+lr] = a1.z; s.As[0][lk4+3][64+lr] = a1.w;
        s.Bs[0][lk4+0][lr]    = b0.x; s.Bs[0][lk4+1][lr]    = b0.y;
        s.Bs[0][lk4+2][lr]    = b0.z; s.Bs[0][lk4+3][lr]    = b0.w;
        s.Bs[0][lk4+0][64+lr] = b1.x; s.Bs[0][lk4+1][64+lr] = b1.y;
        s.Bs[0][lk4+2][64+lr] = b1.z; s.Bs[0][lk4+3][64+lr] = b1.w;
    }
    __syncthreads();

    int buf = 0;
    for (int k0 = KT; k0 <= K; k0 += KT) {
        const bool has_next = (k0 < K);
        float4 a0n, a1n, b0n, b1n;
        if (has_next) {
            a0n = *(const float4*)&A[(size_t)(m0 + lr)      * lda + k0 + lk4];
            a1n = *(const float4*)&A[(size_t)(m0 + 64 + lr) * lda + k0 + lk4];
            b0n = *(const float4*)&B[(size_t)(n0 + lr)      * ldb + k0 + lk4];
            b1n = *(const float4*)&B[(size_t)(n0 + 64 + lr) * ldb + k0 + lk4];
        }

        #pragma unroll
        for (int kk = 0; kk < KT; kk++) {
            float4 av0 = *(const float4*)&s.As[buf][kk][ty * 4];
            float4 av1 = *(const float4*)&s.As[buf][kk][64 + ty * 4];
            float4 bv0 = *(const float4*)&s.Bs[buf][kk][tx * 4];
            float4 bv1 = *(const float4*)&s.Bs[buf][kk][64 + tx * 4];
            const float a[8] = {av0.x, av0.y, av0.z, av0.w, av1.x, av1.y, av1.z, av1.w};
            const float b[8] = {bv0.x, bv0.y, bv0.z, bv0.w, bv1.x, bv1.y, bv1.z, bv1.w};
            #pragma unroll
            for (int i = 0; i < 8; i++)
                #pragma unroll
                for (int j = 0; j < 8; j++)
                    acc[i][j] = fmaf(a[i], b[j], acc[i][j]);
        }

        if (has_next) {
            const int nb = buf ^ 1;
            s.As[nb][lk4+0][lr]    = a0n.x; s.As[nb][lk4+1][lr]    = a0n.y;
            s.As[nb][lk4+2][lr]    = a0n.z; s.As[nb][lk4+3][lr]    = a0n.w;
            s.As[nb][lk4+0][64+lr] = a1n.x; s.As[nb][lk4+1][64+lr] = a1n.y;
            s.As[nb][lk4+2][64+lr] = a1n.z; s.As[nb][lk4+3][64+lr] = a1n.w;
            s.Bs[nb][lk4+0][lr]    = b0n.x; s.Bs[nb][lk4+1][lr]    = b0n.y;
            s.Bs[nb][lk4+2][lr]    = b0n.z; s.Bs[nb][lk4+3][lr]    = b0n.w;
            s.Bs[nb][lk4+0][64+lr] = b1n.x; s.Bs[nb][lk4+1][64+lr] = b1n.y;
            s.Bs[nb][lk4+2][64+lr] = b1n.z; s.Bs[nb][lk4+3][64+lr] = b1n.w;
            __syncthreads();
        }
        buf ^= 1;
    }

    // epilogue: 16 float4 stores
    #pragma unroll
    for (int i = 0; i < 8; i++) {
        const int m = m0 + ((i < 4) ? (ty * 4 + i) : (64 + ty * 4 + i - 4));
        const int nA = n0 + tx * 4;
        const int nB = n0 + 64 + tx * 4;
        float4 r0 = make_float4(acc[i][0], acc[i][1], acc[i][2], acc[i][3]);
        float4 r1 = make_float4(acc[i][4], acc[i][5], acc[i][6], acc[i][7]);
        if (bias) {
            r0.x += bias[nA+0]; r0.y += bias[nA+1]; r0.z += bias[nA+2]; r0.w += bias[nA+3];
            r1.x += bias[nB+0]; r1.y += bias[nB+1]; r1.z += bias[nB+2]; r1.w += bias[nB+3];
        }
        *(float4*)&C[(size_t)m * ldc + nA] = r0;
        *(float4*)&C[(size_t)m * ldc + nB] = r1;
    }
}

// ---------------------------------------------------------------------------
// Projection GEMM: C[M,N] = A[M,K] @ W[N,K]^T (+bias). grid (N/128, M/128).
// ---------------------------------------------------------------------------
__global__ void __launch_bounds__(256, 2)
proj_kernel(const float* __restrict__ A,
            const float* __restrict__ W,
            float* __restrict__ C,
            const float* __restrict__ bias,
            int N, int K)
{
    __shared__ Smem128 s;
    gemm128_body(A, K, W, K, C, N, K, bias, blockIdx.y * 128, blockIdx.x * 128, s);
}

// ---------------------------------------------------------------------------
// scores[b,h] = q_bh @ k_bh^T.  grid (SEQ/128, SEQ/128, BH).
// ---------------------------------------------------------------------------
__global__ void __launch_bounds__(256, 2)
scores_kernel()
{
    __shared__ Smem128 s;
    const int bh = blockIdx.z;
    const int b  = bh >> 4;
    const int h  = bh & 15;
    const float* A = g_q + (size_t)b * SEQ * DMODEL + h * DHEAD;
    const float* B = g_k + (size_t)b * SEQ * DMODEL + h * DHEAD;
    float*       C = g_sc + (size_t)bh * SEQ * SEQ;
    gemm128_body(A, DMODEL, B, DMODEL, C, SEQ, DHEAD, nullptr,
                 blockIdx.y * 128, blockIdx.x * 128, s);
}

// ---------------------------------------------------------------------------
// Row softmax over SEQ=2048 columns. One 256-thread block per row, float4 I/O.
// ---------------------------------------------------------------------------
__global__ void __launch_bounds__(256)
softmax_kernel()
{
    __shared__ float red[8];
    const int tid  = threadIdx.x;
    const int lane = tid & 31;
    const int warp = tid >> 5;
    float4* p4 = reinterpret_cast<float4*>(g_sc + (size_t)blockIdx.x * SEQ);

    float4 x0 = p4[tid];
    float4 x1 = p4[tid + 256];

    float mx = fmaxf(fmaxf(fmaxf(x0.x, x0.y), fmaxf(x0.z, x0.w)),
                     fmaxf(fmaxf(x1.x, x1.y), fmaxf(x1.z, x1.w)));
    #pragma unroll
    for (int o = 16; o > 0; o >>= 1)
        mx = fmaxf(mx, __shfl_xor_sync(0xffffffffu, mx, o));
    if (lane == 0) red[warp] = mx;
    __syncthreads();
    if (warp == 0) {
        float m = red[lane & 7];
        #pragma unroll
        for (int o = 4; o > 0; o >>= 1)
            m = fmaxf(m, __shfl_xor_sync(0xffffffffu, m, o));
        if (lane == 0) red[0] = m;
    }
    __syncthreads();
    mx = red[0];
    __syncthreads();

    x0.x = __expf(x0.x - mx); x0.y = __expf(x0.y - mx);
    x0.z = __expf(x0.z - mx); x0.w = __expf(x0.w - mx);
    x1.x = __expf(x1.x - mx); x1.y = __expf(x1.y - mx);
    x1.z = __expf(x1.z - mx); x1.w = __expf(x1.w - mx);
    float sum = x0.x + x0.y + x0.z + x0.w + x1.x + x1.y + x1.z + x1.w;
    #pragma unroll
    for (int o = 16; o > 0; o >>= 1)
        sum += __shfl_xor_sync(0xffffffffu, sum, o);
    if (lane == 0) red[warp] = sum;
    __syncthreads();
    if (warp == 0) {
        float sm = red[lane & 7];
        #pragma unroll
        for (int o = 4; o > 0; o >>= 1)
            sm += __shfl_xor_sync(0xffffffffu, sm, o);
        if (lane == 0) red[0] = sm;
    }
    __syncthreads();
    const float inv = 1.0f / red[0];

    x0.x *= inv; x0.y *= inv; x0.z *= inv; x0.w *= inv;
    x1.x *= inv; x1.y *= inv; x1.z *= inv; x1.w *= inv;
    p4[tid]       = x0;
    p4[tid + 256] = x1;
}

// ---------------------------------------------------------------------------
// attn_bh (SEQ x 64) = P_bh (SEQ x SEQ) @ v_bh (SEQ x 64). NN GEMM.
// Tile 128x64, 256 threads, 8x4 microtile, double-buffered.
// grid (1, SEQ/128, BH).
// ---------------------------------------------------------------------------
__global__ void __launch_bounds__(256, 2)
pv_kernel()
{
    __shared__ float As[2][KT][132];
    __shared__ float Bs[2][KT][68];

    const int bh = blockIdx.z;
    const int b  = bh >> 4;
    const int h  = bh & 15;
    const float* A = g_sc   + (size_t)bh * SEQ * SEQ;                 // lda = SEQ
    const float* B = g_v    + (size_t)b * SEQ * DMODEL + h * DHEAD;   // ldb = DMODEL
    float*       C = g_attn + (size_t)b * SEQ * DMODEL + h * DHEAD;   // ldc = DMODEL

    const int tid = threadIdx.x;
    const int tx  = tid & 15;          // cols tx*4 .. tx*4+3
    const int ty  = tid >> 4;          // rows ty*4, 64+ty*4
    const int lr  = tid >> 2;          // A-load row 0..63
    const int lk4 = (tid & 3) * 4;     // A-load k 0,4,8,12
    const int bk  = tid >> 4;          // B-load k 0..15
    const int bn  = (tid & 15) * 4;    // B-load col

    const int m0 = blockIdx.y * 128;

    float acc[8][4] = {};

    // prologue
    {
        float4 a0 = *(const float4*)&A[(size_t)(m0 + lr)      * SEQ + lk4];
        float4 a1 = *(const float4*)&A[(size_t)(m0 + 64 + lr) * SEQ + lk4];
        float4 bv = *(const float4*)&B[(size_t)bk * DMODEL + bn];
        As[0][lk4+0][lr]    = a0.x; As[0][lk4+1][lr]    = a0.y;
        As[0][lk4+2][lr]    = a0.z; As[0][lk4+3][lr]    = a0.w;
        As[0][lk4+0][64+lr] = a1.x; As[0][lk4+1][64+lr] = a1.y;
        As[0][lk4+2][64+lr] = a1.z; As[0][lk4+3][64+lr] = a1.w;
        *(float4*)&Bs[0][bk][bn] = bv;
    }
    __syncthreads();

    int buf = 0;
    for (int k0 = KT; k0 <= SEQ; k0 += KT) {
        const bool has_next = (k0 < SEQ);
        float4 a0n, a1n, bvn;
        if (has_next) {
            a0n = *(const float4*)&A[(size_t)(m0 + lr)      * SEQ + k0 + lk4];
            a1n = *(const float4*)&A[(size_t)(m0 + 64 + lr) * SEQ + k0 + lk4];
            bvn = *(const float4*)&B[(size_t)(k0 + bk) * DMODEL + bn];
        }

        #pragma unroll
        for (int kk = 0; kk < KT; kk++) {
            float4 av0 = *(const float4*)&As[buf][kk][ty * 4];
            float4 av1 = *(const float4*)&As[buf][kk][64 + ty * 4];
            float4 bv  = *(const float4*)&Bs[buf][kk][tx * 4];
            const float a[8] = {av0.x, av0.y, av0.z, av0.w, av1.x, av1.y, av1.z, av1.w};
            const float bb[4] = {bv.x, bv.y, bv.z, bv.w};
            #pragma unroll
            for (int i = 0; i < 8; i++)
                #pragma unroll
                for (int j = 0; j < 4; j++)
                    acc[i][j] = fmaf(a[i], bb[j], acc[i][j]);
        }

        if (has_next) {
            const int nb = buf ^ 1;
            As[nb][lk4+0][lr]    = a0n.x; As[nb][lk4+1][lr]    = a0n.y;
            As[nb][lk4+2][lr]    = a0n.z; As[nb][lk4+3][lr]    = a0n.w;
            As[nb][lk4+0][64+lr] = a1n.x; As[nb][lk4+1][64+lr] = a1n.y;
            As[nb][lk4+2][64+lr] = a1n.z; As[nb][lk4+3][64+lr] = a1n.w;
            *(float4*)&Bs[nb][bk][bn] = bvn;
            __syncthreads();
        }
        buf ^= 1;
    }

    #pragma unroll
    for (int i = 0; i < 8; i++) {
        const int m = m0 + ((i < 4) ? (ty * 4 + i) : (64 + ty * 4 + i - 4));
        *(float4*)&C[(size_t)m * DMODEL + tx * 4] =
            make_float4(acc[i][0], acc[i][1], acc[i][2], acc[i][3]);
    }
}

// ---------------------------------------------------------------------------
extern "C" void kernel_launch(void* const* d_in, const int* in_sizes, int n_in,
                              void* d_out, int out_size)
{
    const float* x  = (const float*)d_in[0];
    // d_in[1] = attn_weights (unused by reference forward)
    const float* Wq = (const float*)d_in[2];
    const float* Wk = (const float*)d_in[3];
    const float* Wv = (const float*)d_in[4];
    const float* Wp = (const float*)d_in[5];
    const float* bp = (const float*)d_in[6];
    float* out = (float*)d_out;

    float *q, *k, *v, *attn;
    cudaGetSymbolAddress((void**)&q,    g_q);
    cudaGetSymbolAddress((void**)&k,    g_k);
    cudaGetSymbolAddress((void**)&v,    g_v);
    cudaGetSymbolAddress((void**)&attn, g_attn);

    const dim3 blk(256);
    const dim3 grid_proj(DMODEL / 128, MROWS / 128);   // (8, 32)

    // QKV projections
    proj_kernel<<<grid_proj, blk>>>(x, Wq, q, nullptr, DMODEL, DMODEL);
    proj_kernel<<<grid_proj, blk>>>(x, Wk, k, nullptr, DMODEL, DMODEL);
    proj_kernel<<<grid_proj, blk>>>(x, Wv, v, nullptr, DMODEL, DMODEL);

    // Attention
    scores_kernel <<<dim3(SEQ / 128, SEQ / 128, BH), blk>>>();
    softmax_kernel<<<BH * SEQ, blk>>>();
    pv_kernel     <<<dim3(1, SEQ / 128, BH), blk>>>();

    // Output projection (+bias)
    proj_kernel<<<grid_proj, blk>>>(attn, Wp, out, bp, DMODEL, DMODEL);
}